// round 1
// baseline (speedup 1.0000x reference)
#include <cuda_runtime.h>

#define KF_B 2048
#define KF_T 512
#define KF_D 8
#define KF_M 2

// Output layout (float offsets): means, covs, Rs, Hs concatenated.
#define OFF_MEANS 0
#define OFF_COVS  (KF_B * KF_T * KF_D)                       // 8388608
#define OFF_RS    (OFF_COVS + KF_B * KF_T * KF_D * KF_D)     // 75497472
#define OFF_HS    (OFF_RS + KF_B * KF_T * KF_M * KF_M)       // 79691776

#define SCAN_BLOCKS (KF_B / 4)   // 512 blocks, 4 chains per 32-thread block
#define FILL_BLOCKS 256

__global__ void __launch_bounds__(32) kf_kernel(
    const float* __restrict__ xin_g,   // [B,T,M]
    const float* __restrict__ mean0,   // [B,D]
    const float* __restrict__ cov0,    // [B,D,D]
    const float* __restrict__ Fg,      // [D,D]
    const float* __restrict__ Hg,      // [M,D]
    const float* __restrict__ Qg,      // [D,D]
    const float* __restrict__ Rg,      // [M,M]
    float* __restrict__ out)
{
    // ---------------- broadcast-fill blocks (Rs, Hs) ----------------
    if (blockIdx.x >= SCAN_BLOCKS) {
        const size_t BT = (size_t)KF_B * KF_T;
        float4 r4 = *(const float4*)Rg;                  // R = 4 floats = one float4
        float4 h0 = *(const float4*)(Hg + 0);
        float4 h1 = *(const float4*)(Hg + 4);
        float4 h2 = *(const float4*)(Hg + 8);
        float4 h3 = *(const float4*)(Hg + 12);
        float4* Rs = (float4*)(out + OFF_RS);
        float4* Hs = (float4*)(out + OFF_HS);
        const size_t nthr   = (size_t)FILL_BLOCKS * 32;
        const size_t tid    = (size_t)(blockIdx.x - SCAN_BLOCKS) * 32 + threadIdx.x;
        for (size_t i = tid; i < BT; i += nthr)
            Rs[i] = r4;
        for (size_t i = tid; i < BT; i += nthr) {
            float4* p = Hs + i * 4;
            p[0] = h0; p[1] = h1; p[2] = h2; p[3] = h3;
        }
        return;
    }

    // ---------------- scan blocks: 4 chains/block, 8 lanes/chain ----------------
    const int lane = threadIdx.x & 31;
    const int g    = lane >> 3;        // chain within block
    const int e    = lane & 7;         // state row owned by this lane
    const int b    = blockIdx.x * 4 + g;

    // Static matrices in registers (replicated; registers are free at this occupancy)
    float F[8][8];
#pragma unroll
    for (int i = 0; i < 8; ++i) {
        float4 a = *(const float4*)(Fg + i * 8);
        float4 c = *(const float4*)(Fg + i * 8 + 4);
        F[i][0] = a.x; F[i][1] = a.y; F[i][2] = a.z; F[i][3] = a.w;
        F[i][4] = c.x; F[i][5] = c.y; F[i][6] = c.z; F[i][7] = c.w;
    }
    float H0[8], H1[8];
    {
        float4 a = *(const float4*)(Hg + 0);
        float4 c = *(const float4*)(Hg + 4);
        H0[0]=a.x; H0[1]=a.y; H0[2]=a.z; H0[3]=a.w;
        H0[4]=c.x; H0[5]=c.y; H0[6]=c.z; H0[7]=c.w;
        float4 d = *(const float4*)(Hg + 8);
        float4 f = *(const float4*)(Hg + 12);
        H1[0]=d.x; H1[1]=d.y; H1[2]=d.z; H1[3]=d.w;
        H1[4]=f.x; H1[5]=f.y; H1[6]=f.z; H1[7]=f.w;
    }
    float Qr[8];
    {
        float4 a = *(const float4*)(Qg + e * 8);
        float4 c = *(const float4*)(Qg + e * 8 + 4);
        Qr[0]=a.x; Qr[1]=a.y; Qr[2]=a.z; Qr[3]=a.w;
        Qr[4]=c.x; Qr[5]=c.y; Qr[6]=c.z; Qr[7]=c.w;
    }
    const float r00 = Rg[0], r01 = Rg[1], r11 = Rg[3];

    // State: lane e holds cov row e (symmetric) + mean[e]
    float cov[8];
    {
        float4 a = *(const float4*)(cov0 + b * 64 + e * 8);
        float4 c = *(const float4*)(cov0 + b * 64 + e * 8 + 4);
        cov[0]=a.x; cov[1]=a.y; cov[2]=a.z; cov[3]=a.w;
        cov[4]=c.x; cov[5]=c.y; cov[6]=c.z; cov[7]=c.w;
    }
    float mean_e = mean0[b * 8 + e];

    float* outM = out + OFF_MEANS + (size_t)b * (KF_T * KF_D);
    float* outC = out + OFF_COVS  + (size_t)b * (KF_T * KF_D * KF_D);
    const float* xrow = xin_g + (size_t)b * (KF_T * KF_M);

    // SMEM exchange buffers — strides chosen bank-conflict-free (verified per phase)
    __shared__ __align__(16) float sHP[4 * 24];   // [g]: hp0[0..7] @0, hp1[0..7] @8
    __shared__ __align__(16) float sMu[4 * 8];
    __shared__ __align__(16) float sT1[4 * 104];  // row stride 12, group stride 104

    float2 x = *(const float2*)xrow;   // prefetch t=0

#pragma unroll 1
    for (int t = 0; t < KF_T; ++t) {
        // emit state BEFORE consuming x_t (1-step-ahead prediction semantics)
        outM[t * 8 + e] = mean_e;
        float4* oc = (float4*)(outC + t * 64 + e * 8);
        oc[0] = make_float4(cov[0], cov[1], cov[2], cov[3]);
        oc[1] = make_float4(cov[4], cov[5], cov[6], cov[7]);

        int tn = (t + 1 < KF_T) ? t + 1 : t;
        float2 xn = *(const float2*)(xrow + tn * 2);

        // HP[m][e] = dot(H[m,:], cov_row_e)  (uses cov symmetry -> lane-local)
        float hp0 = 0.f, hp1 = 0.f;
#pragma unroll
        for (int j = 0; j < 8; ++j) {
            hp0 = fmaf(H0[j], cov[j], hp0);
            hp1 = fmaf(H1[j], cov[j], hp1);
        }

        // Butterfly-reduce S entries and H*mean over the 8-lane group
        float p0 = hp0 * H0[e];
        float p1 = hp0 * H1[e];
        float p2 = hp1 * H1[e];
        float p3 = H0[e] * mean_e;
        float p4 = H1[e] * mean_e;
#pragma unroll
        for (int w = 1; w < 8; w <<= 1) {
            p0 += __shfl_xor_sync(0xffffffffu, p0, w);
            p1 += __shfl_xor_sync(0xffffffffu, p1, w);
            p2 += __shfl_xor_sync(0xffffffffu, p2, w);
            p3 += __shfl_xor_sync(0xffffffffu, p3, w);
            p4 += __shfl_xor_sync(0xffffffffu, p4, w);
        }
        const float S00 = p0 + r00, S01 = p1 + r01, S11 = p2 + r11;
        const float idet = __fdividef(1.0f, fmaf(S00, S11, -S01 * S01));
        const float i00 = S11 * idet, i01 = -S01 * idet, i11 = S00 * idet;
        const float Kt0 = i00 * hp0 + i01 * hp1;   // Kt[0][e]
        const float Kt1 = i01 * hp0 + i11 * hp1;   // Kt[1][e]
        const float rs0 = x.x - p3;
        const float rs1 = x.y - p4;
        const float mu  = fmaf(Kt0, rs0, fmaf(Kt1, rs1, mean_e));   // mean_u[e]

        // Exchange HP rows + mean_u through SMEM
        sHP[g * 24 + e]     = hp0;
        sHP[g * 24 + 8 + e] = hp1;
        sMu[g * 8 + e]      = mu;
        __syncwarp();

        const float4 A0 = *(const float4*)&sHP[g * 24 + 0];
        const float4 A1 = *(const float4*)&sHP[g * 24 + 4];
        const float4 B0 = *(const float4*)&sHP[g * 24 + 8];
        const float4 B1 = *(const float4*)&sHP[g * 24 + 12];
        float cu[8];
        cu[0] = cov[0] - Kt0 * A0.x - Kt1 * B0.x;
        cu[1] = cov[1] - Kt0 * A0.y - Kt1 * B0.y;
        cu[2] = cov[2] - Kt0 * A0.z - Kt1 * B0.z;
        cu[3] = cov[3] - Kt0 * A0.w - Kt1 * B0.w;
        cu[4] = cov[4] - Kt0 * A1.x - Kt1 * B1.x;
        cu[5] = cov[5] - Kt0 * A1.y - Kt1 * B1.y;
        cu[6] = cov[6] - Kt0 * A1.z - Kt1 * B1.z;
        cu[7] = cov[7] - Kt0 * A1.w - Kt1 * B1.w;

        // mean_p[e] = dot(F[e,:], mean_u)
        const float4 M0 = *(const float4*)&sMu[g * 8 + 0];
        const float4 M1 = *(const float4*)&sMu[g * 8 + 4];
        float mp = F[e][0] * M0.x;
        mp = fmaf(F[e][1], M0.y, mp);
        mp = fmaf(F[e][2], M0.z, mp);
        mp = fmaf(F[e][3], M0.w, mp);
        mp = fmaf(F[e][4], M1.x, mp);
        mp = fmaf(F[e][5], M1.y, mp);
        mp = fmaf(F[e][6], M1.z, mp);
        mp = fmaf(F[e][7], M1.w, mp);

        // T1[e][j] = dot(cov_u_row_e, F[j,:])  ( = (cov_u * F^T) row e )
        float T1v[8];
#pragma unroll
        for (int j = 0; j < 8; ++j) {
            float s = 0.f;
#pragma unroll
            for (int k = 0; k < 8; ++k) s = fmaf(cu[k], F[j][k], s);
            T1v[j] = s;
        }
        *(float4*)&sT1[g * 104 + e * 12]     = make_float4(T1v[0], T1v[1], T1v[2], T1v[3]);
        *(float4*)&sT1[g * 104 + e * 12 + 4] = make_float4(T1v[4], T1v[5], T1v[6], T1v[7]);
        __syncwarp();

        // cov_p row e = sum_k F[e][k] * T1_row_k + Q_row_e
        float cp[8];
#pragma unroll
        for (int j = 0; j < 8; ++j) cp[j] = Qr[j];
#pragma unroll
        for (int k = 0; k < 8; ++k) {
            const float fk = F[e][k];
            const float4 u = *(const float4*)&sT1[g * 104 + k * 12];
            const float4 v = *(const float4*)&sT1[g * 104 + k * 12 + 4];
            cp[0] = fmaf(fk, u.x, cp[0]);
            cp[1] = fmaf(fk, u.y, cp[1]);
            cp[2] = fmaf(fk, u.z, cp[2]);
            cp[3] = fmaf(fk, u.w, cp[3]);
            cp[4] = fmaf(fk, v.x, cp[4]);
            cp[5] = fmaf(fk, v.y, cp[5]);
            cp[6] = fmaf(fk, v.z, cp[6]);
            cp[7] = fmaf(fk, v.w, cp[7]);
        }

#pragma unroll
        for (int j = 0; j < 8; ++j) cov[j] = cp[j];
        mean_e = mp;
        x = xn;
        // NOTE: no sync needed here — next iteration's first SMEM writes (sHP/sMu)
        // are ordered after this iteration's reads by the sT1 __syncwarp above /
        // next iteration's first __syncwarp.
    }
}

extern "C" void kernel_launch(void* const* d_in, const int* in_sizes, int n_in,
                              void* d_out, int out_size)
{
    (void)in_sizes; (void)n_in; (void)out_size;
    const float* xin   = (const float*)d_in[0];
    const float* mean0 = (const float*)d_in[1];
    const float* cov0  = (const float*)d_in[2];
    const float* F     = (const float*)d_in[3];
    const float* H     = (const float*)d_in[4];
    const float* Q     = (const float*)d_in[5];
    const float* R     = (const float*)d_in[6];
    float* out = (float*)d_out;

    kf_kernel<<<SCAN_BLOCKS + FILL_BLOCKS, 32>>>(xin, mean0, cov0, F, H, Q, R, out);
}

// round 3
// speedup vs baseline: 1.3134x; 1.3134x over previous
#include <cuda_runtime.h>

#define KF_B 2048
#define KF_T 512
#define KF_D 8
#define KF_M 2

// Output layout (float offsets): means, covs, Rs, Hs concatenated.
#define OFF_MEANS 0
#define OFF_COVS  (KF_B * KF_T * KF_D)                       // 8388608
#define OFF_RS    (OFF_COVS + KF_B * KF_T * KF_D * KF_D)     // 75497472
#define OFF_HS    (OFF_RS + KF_B * KF_T * KF_M * KF_M)       // 79691776

#define SCAN_BLOCKS (KF_B / 4)   // 512 blocks, 4 chains per 32-thread block
#define FILL_BLOCKS 256

typedef unsigned long long ull;

__device__ __forceinline__ ull ff_pack2(float lo, float hi) {
    ull r;
    asm("mov.b64 %0, {%1, %2};" : "=l"(r) : "f"(lo), "f"(hi));
    return r;
}
__device__ __forceinline__ ull ff_dup(float v) { return ff_pack2(v, v); }
__device__ __forceinline__ ull ff_fma2(ull a, ull b, ull c) {
    ull r;
    asm("fma.rn.f32x2 %0, %1, %2, %3;" : "=l"(r) : "l"(a), "l"(b), "l"(c));
    return r;
}
__device__ __forceinline__ float2 ff_unpack(ull v) {
    float2 r;
    asm("mov.b64 {%0, %1}, %2;" : "=f"(r.x), "=f"(r.y) : "l"(v));
    return r;
}

__global__ void __launch_bounds__(32) kf_kernel(
    const float* __restrict__ xin_g,   // [B,T,M]
    const float* __restrict__ mean0,   // [B,D]
    const float* __restrict__ cov0,    // [B,D,D]
    const float* __restrict__ Fg,      // [D,D]
    const float* __restrict__ Hg,      // [M,D]
    const float* __restrict__ Qg,      // [D,D]
    const float* __restrict__ Rg,      // [M,M]
    float* __restrict__ out)
{
    // ---------------- broadcast-fill blocks (Rs, Hs) ----------------
    if (blockIdx.x >= SCAN_BLOCKS) {
        const size_t BT = (size_t)KF_B * KF_T;
        float4 r4 = *(const float4*)Rg;
        float4 h0 = *(const float4*)(Hg + 0);
        float4 h1 = *(const float4*)(Hg + 4);
        float4 h2 = *(const float4*)(Hg + 8);
        float4 h3 = *(const float4*)(Hg + 12);
        float4* Rs = (float4*)(out + OFF_RS);
        float4* Hs = (float4*)(out + OFF_HS);
        const size_t nthr = (size_t)FILL_BLOCKS * 32;
        const size_t tid  = (size_t)(blockIdx.x - SCAN_BLOCKS) * 32 + threadIdx.x;
        for (size_t i = tid; i < BT; i += nthr)
            Rs[i] = r4;
        for (size_t i = tid; i < BT; i += nthr) {
            float4* p = Hs + i * 4;
            p[0] = h0; p[1] = h1; p[2] = h2; p[3] = h3;
        }
        return;
    }

    // ---------------- scan blocks: 4 chains/block, 8 lanes/chain ----------------
    const int lane = threadIdx.x & 31;
    const int g    = lane >> 3;        // chain within block
    const int e    = lane & 7;         // state row owned by this lane
    const int b    = blockIdx.x * 4 + g;

    // ---- loop-invariant registers ----
    // Frow = F[e][:]  (used for mean_p and as scalars for cov_p)
    float Frow[8];
#pragma unroll
    for (int j = 0; j < 8; ++j) Frow[j] = Fg[e * 8 + j];

    // Fpack[k][p] = (F[2p][k], F[2p+1][k])  — transposed pair-packed for T1 FFMA2
    ull Fpack[8][4];
#pragma unroll
    for (int k = 0; k < 8; ++k)
#pragma unroll
        for (int p = 0; p < 4; ++p)
            Fpack[k][p] = ff_pack2(Fg[(2 * p) * 8 + k], Fg[(2 * p + 1) * 8 + k]);

    float H0[8], H1[8];
#pragma unroll
    for (int j = 0; j < 8; ++j) { H0[j] = Hg[j]; H1[j] = Hg[8 + j]; }

    // HF[m][j] = (H F)[m][j]  — lets hm = H*mean_p be computed locally from mean_u
    float HF0[8], HF1[8];
#pragma unroll
    for (int j = 0; j < 8; ++j) {
        float a0 = 0.f, a1 = 0.f;
#pragma unroll
        for (int k = 0; k < 8; ++k) {
            a0 = fmaf(H0[k], Fg[k * 8 + j], a0);
            a1 = fmaf(H1[k], Fg[k * 8 + j], a1);
        }
        HF0[j] = a0; HF1[j] = a1;
    }

    // Q row e as packed pairs (cov_p accumulator init)
    ull Qp[4];
#pragma unroll
    for (int p = 0; p < 4; ++p)
        Qp[p] = ff_pack2(Qg[e * 8 + 2 * p], Qg[e * 8 + 2 * p + 1]);

    const float r00 = Rg[0], r01 = Rg[1], r11 = Rg[3];

    // ---- per-chain state ----
    float cov[8];
    {
        float4 a = *(const float4*)(cov0 + b * 64 + e * 8);
        float4 c = *(const float4*)(cov0 + b * 64 + e * 8 + 4);
        cov[0]=a.x; cov[1]=a.y; cov[2]=a.z; cov[3]=a.w;
        cov[4]=c.x; cov[5]=c.y; cov[6]=c.z; cov[7]=c.w;
    }
    float mean_e = mean0[b * 8 + e];
    // hm = H * mean  (current, pre-update mean)
    float hm0, hm1;
    {
        float4 a = *(const float4*)(mean0 + b * 8);
        float4 c = *(const float4*)(mean0 + b * 8 + 4);
        float m[8] = {a.x,a.y,a.z,a.w,c.x,c.y,c.z,c.w};
        float s0 = 0.f, s1 = 0.f;
#pragma unroll
        for (int j = 0; j < 8; ++j) {
            s0 = fmaf(H0[j], m[j], s0);
            s1 = fmaf(H1[j], m[j], s1);
        }
        hm0 = s0; hm1 = s1;
    }

    float* outM = out + OFF_MEANS + (size_t)b * (KF_T * KF_D);
    float* outC = out + OFF_COVS  + (size_t)b * (KF_T * KF_D * KF_D);
    const float* xrow = xin_g + (size_t)b * (KF_T * KF_M);

    // SMEM exchange buffers — bank-conflict-free layouts (verified per phase)
    __shared__ __align__(16) float sHP[4 * 24];   // [g]: hp0[0..7] @0, hp1[0..7] @8
    __shared__ __align__(16) float sMu[4 * 8];
    __shared__ __align__(16) float sT1[4 * 104];  // row stride 12, group stride 104

    float2 x = *(const float2*)xrow;   // prefetch t=0

#pragma unroll 1
    for (int t = 0; t < KF_T; ++t) {
        // emit state BEFORE consuming x_t (1-step-ahead semantics)
        outM[t * 8 + e] = mean_e;
        float4* oc = (float4*)(outC + t * 64 + e * 8);
        oc[0] = make_float4(cov[0], cov[1], cov[2], cov[3]);
        oc[1] = make_float4(cov[4], cov[5], cov[6], cov[7]);

        int tn = (t + 1 < KF_T) ? t + 1 : t;
        float2 xn = *(const float2*)(xrow + tn * 2);

        // HP[m][e] = dot(H[m,:], cov_row_e)  (cov symmetry -> lane-local)
        float hp0 = 0.f, hp1 = 0.f;
#pragma unroll
        for (int j = 0; j < 8; ++j) {
            hp0 = fmaf(H0[j], cov[j], hp0);
            hp1 = fmaf(H1[j], cov[j], hp1);
        }

        // Exchange HP rows FIRST (S is then computed locally — no shuffles)
        sHP[g * 24 + e]     = hp0;
        sHP[g * 24 + 8 + e] = hp1;
        __syncwarp();

        const float4 A0 = *(const float4*)&sHP[g * 24 + 0];
        const float4 A1 = *(const float4*)&sHP[g * 24 + 4];
        const float4 B0 = *(const float4*)&sHP[g * 24 + 8];
        const float4 B1 = *(const float4*)&sHP[g * 24 + 12];
        const float A[8] = {A0.x,A0.y,A0.z,A0.w,A1.x,A1.y,A1.z,A1.w};
        const float Bv[8] = {B0.x,B0.y,B0.z,B0.w,B1.x,B1.y,B1.z,B1.w};

        // S entries computed locally from full HP rows
        float S00 = r00, S01 = r01, S11 = r11;
#pragma unroll
        for (int j = 0; j < 8; ++j) {
            S00 = fmaf(H0[j], A[j], S00);
            S01 = fmaf(H1[j], A[j], S01);
            S11 = fmaf(H1[j], Bv[j], S11);
        }
        const float idet = __fdividef(1.0f, fmaf(S00, S11, -S01 * S01));
        const float i00 = S11 * idet, i01 = -S01 * idet, i11 = S00 * idet;
        const float Kt0 = i00 * hp0 + i01 * hp1;   // Kt[0][e]
        const float Kt1 = i01 * hp0 + i11 * hp1;   // Kt[1][e]
        const float rs0 = x.x - hm0;
        const float rs1 = x.y - hm1;
        const float mu  = fmaf(Kt0, rs0, fmaf(Kt1, rs1, mean_e));   // mean_u[e]
        sMu[g * 8 + e] = mu;

        // cov_u row e
        float cu[8];
#pragma unroll
        for (int j = 0; j < 8; ++j)
            cu[j] = cov[j] - Kt0 * A[j] - Kt1 * Bv[j];

        // T1 row e = cov_u_row_e * F^T, pair-packed FFMA2
        ull t01 = 0ull, t23 = 0ull, t45 = 0ull, t67 = 0ull;
#pragma unroll
        for (int k = 0; k < 8; ++k) {
            const ull ck = ff_dup(cu[k]);
            t01 = ff_fma2(ck, Fpack[k][0], t01);
            t23 = ff_fma2(ck, Fpack[k][1], t23);
            t45 = ff_fma2(ck, Fpack[k][2], t45);
            t67 = ff_fma2(ck, Fpack[k][3], t67);
        }
        {
            const float2 u0 = ff_unpack(t01), u1 = ff_unpack(t23);
            const float2 u2 = ff_unpack(t45), u3 = ff_unpack(t67);
            *(float4*)&sT1[g * 104 + e * 12]     = make_float4(u0.x, u0.y, u1.x, u1.y);
            *(float4*)&sT1[g * 104 + e * 12 + 4] = make_float4(u2.x, u2.y, u3.x, u3.y);
        }
        __syncwarp();

        // mean_p[e] = F[e,:] . mean_u ; hm_next = (HF) . mean_u (local!)
        const float4 M0 = *(const float4*)&sMu[g * 8 + 0];
        const float4 M1 = *(const float4*)&sMu[g * 8 + 4];
        const float Mu[8] = {M0.x,M0.y,M0.z,M0.w,M1.x,M1.y,M1.z,M1.w};
        float mp = 0.f, nh0 = 0.f, nh1 = 0.f;
#pragma unroll
        for (int j = 0; j < 8; ++j) {
            mp  = fmaf(Frow[j], Mu[j], mp);
            nh0 = fmaf(HF0[j],  Mu[j], nh0);
            nh1 = fmaf(HF1[j],  Mu[j], nh1);
        }

        // cov_p row e = sum_k F[e][k] * T1_row_k + Q_row_e  (pair-packed FFMA2)
        ull cp01 = Qp[0], cp23 = Qp[1], cp45 = Qp[2], cp67 = Qp[3];
#pragma unroll
        for (int k = 0; k < 8; ++k) {
            const ull fk2 = ff_dup(Frow[k]);
            const ulonglong2 u = *(const ulonglong2*)&sT1[g * 104 + k * 12];
            const ull v0 = *(const ull*)&sT1[g * 104 + k * 12 + 4];
            const ull v1 = *(const ull*)&sT1[g * 104 + k * 12 + 6];
            cp01 = ff_fma2(fk2, u.x, cp01);
            cp23 = ff_fma2(fk2, u.y, cp23);
            cp45 = ff_fma2(fk2, v0,  cp45);
            cp67 = ff_fma2(fk2, v1,  cp67);
        }
        {
            const float2 c0 = ff_unpack(cp01), c1 = ff_unpack(cp23);
            const float2 c2 = ff_unpack(cp45), c3 = ff_unpack(cp67);
            cov[0]=c0.x; cov[1]=c0.y; cov[2]=c1.x; cov[3]=c1.y;
            cov[4]=c2.x; cov[5]=c2.y; cov[6]=c3.x; cov[7]=c3.y;
        }
        mean_e = mp;
        hm0 = nh0; hm1 = nh1;
        x = xn;
        // Race-freedom: all sHP reads are before the 2nd syncwarp; all sMu/sT1
        // reads are before the next iteration's 1st syncwarp; writes to each
        // buffer sit on the opposite side of the corresponding barrier.
    }
}

extern "C" void kernel_launch(void* const* d_in, const int* in_sizes, int n_in,
                              void* d_out, int out_size)
{
    (void)in_sizes; (void)n_in; (void)out_size;
    const float* xin   = (const float*)d_in[0];
    const float* mean0 = (const float*)d_in[1];
    const float* cov0  = (const float*)d_in[2];
    const float* F     = (const float*)d_in[3];
    const float* H     = (const float*)d_in[4];
    const float* Q     = (const float*)d_in[5];
    const float* R     = (const float*)d_in[6];
    float* out = (float*)d_out;

    kf_kernel<<<SCAN_BLOCKS + FILL_BLOCKS, 32>>>(xin, mean0, cov0, F, H, Q, R, out);
}

// round 4
// speedup vs baseline: 1.4107x; 1.0741x over previous
#include <cuda_runtime.h>

#define KF_B 2048
#define KF_T 512
#define KF_D 8
#define KF_M 2

// Output layout (float offsets): means, covs, Rs, Hs concatenated.
#define OFF_MEANS 0
#define OFF_COVS  (KF_B * KF_T * KF_D)                       // 8388608
#define OFF_RS    (OFF_COVS + KF_B * KF_T * KF_D * KF_D)     // 75497472
#define OFF_HS    (OFF_RS + KF_B * KF_T * KF_M * KF_M)       // 79691776

#define SCAN_BLOCKS (KF_B / 2)   // 1024 blocks, 2 chains per 32-thread block
#define FILL_BLOCKS 256

typedef unsigned long long ull;

__device__ __forceinline__ ull ff_pack2(float lo, float hi) {
    ull r;
    asm("mov.b64 %0, {%1, %2};" : "=l"(r) : "f"(lo), "f"(hi));
    return r;
}
__device__ __forceinline__ ull ff_dup(float v) { return ff_pack2(v, v); }
__device__ __forceinline__ ull ff_fma2(ull a, ull b, ull c) {
    ull r;
    asm("fma.rn.f32x2 %0, %1, %2, %3;" : "=l"(r) : "l"(a), "l"(b), "l"(c));
    return r;
}
__device__ __forceinline__ ull ff_add2(ull a, ull b) {
    ull r;
    asm("add.rn.f32x2 %0, %1, %2;" : "=l"(r) : "l"(a), "l"(b));
    return r;
}
__device__ __forceinline__ float2 ff_unpack(ull v) {
    float2 r;
    asm("mov.b64 {%0, %1}, %2;" : "=f"(r.x), "=f"(r.y) : "l"(v));
    return r;
}
// 64-bit shfl_xor(8) as two 32-bit shuffles
__device__ __forceinline__ ull shflx8_64(ull v) {
    float2 p = ff_unpack(v);
    p.x = __shfl_xor_sync(0xffffffffu, p.x, 8);
    p.y = __shfl_xor_sync(0xffffffffu, p.y, 8);
    return ff_pack2(p.x, p.y);
}

__global__ void __launch_bounds__(32) kf_kernel(
    const float* __restrict__ xin_g,   // [B,T,M]
    const float* __restrict__ mean0,   // [B,D]
    const float* __restrict__ cov0,    // [B,D,D]
    const float* __restrict__ Fg,      // [D,D]
    const float* __restrict__ Hg,      // [M,D]
    const float* __restrict__ Qg,      // [D,D]
    const float* __restrict__ Rg,      // [M,M]
    float* __restrict__ out)
{
    // ---------------- broadcast-fill blocks (Rs, Hs) ----------------
    if (blockIdx.x >= SCAN_BLOCKS) {
        const size_t BT = (size_t)KF_B * KF_T;
        float4 r4 = *(const float4*)Rg;
        float4 h0v = *(const float4*)(Hg + 0);
        float4 h1v = *(const float4*)(Hg + 4);
        float4 h2v = *(const float4*)(Hg + 8);
        float4 h3v = *(const float4*)(Hg + 12);
        float4* Rs = (float4*)(out + OFF_RS);
        float4* Hs = (float4*)(out + OFF_HS);
        const size_t nthr = (size_t)FILL_BLOCKS * 32;
        const size_t tid  = (size_t)(blockIdx.x - SCAN_BLOCKS) * 32 + threadIdx.x;
        for (size_t i = tid; i < BT; i += nthr)
            Rs[i] = r4;
        for (size_t i = tid; i < BT; i += nthr) {
            float4* p = Hs + i * 4;
            p[0] = h0v; p[1] = h1v; p[2] = h2v; p[3] = h3v;
        }
        return;
    }

    // ---------------- scan: 2 chains/warp, 16 lanes/chain ----------------
    // lane = g*16 + h*8 + e : chain g, half h (k/j range [4h,4h+4)), state row e
    const int lane = threadIdx.x & 31;
    const int g    = lane >> 4;
    const int sub  = lane & 15;
    const int e    = sub & 7;
    const int h    = sub >> 3;
    const int b    = blockIdx.x * 2 + g;
    const bool h0  = (h == 0);
    const int j0   = 4 * h;            // global offset of this lane's half

    // ---- loop-invariant registers ----
    float H0h[4], H1h[4];              // H[m][j0+i]
#pragma unroll
    for (int i = 0; i < 4; ++i) { H0h[i] = Hg[j0 + i]; H1h[i] = Hg[8 + j0 + i]; }

    float Frow[8];                     // F[e][:]
#pragma unroll
    for (int j = 0; j < 8; ++j) Frow[j] = Fg[e * 8 + j];
    float Frh[4];                      // F[e][j0+i]
#pragma unroll
    for (int i = 0; i < 4; ++i) Frh[i] = Fg[e * 8 + j0 + i];

    // HF[m][j] for j in this half (lets hm = H*mean_p be tracked locally)
    float HF0h[4], HF1h[4];
#pragma unroll
    for (int i = 0; i < 4; ++i) {
        const int j = j0 + i;
        float a0 = 0.f, a1 = 0.f;
#pragma unroll
        for (int k = 0; k < 8; ++k) {
            a0 = fmaf(Hg[k],     Fg[k * 8 + j], a0);
            a1 = fmaf(Hg[8 + k], Fg[k * 8 + j], a1);
        }
        HF0h[i] = a0; HF1h[i] = a1;
    }

    // Fpk[kk][p] = (F[2p][j0+kk], F[2p+1][j0+kk])   (T1 partial operands)
    ull Fpk[4][4];
#pragma unroll
    for (int kk = 0; kk < 4; ++kk)
#pragma unroll
        for (int p = 0; p < 4; ++p)
            Fpk[kk][p] = ff_pack2(Fg[(2 * p) * 8 + j0 + kk], Fg[(2 * p + 1) * 8 + j0 + kk]);

    // Q[e][half] packed pairs (cov_p accumulator init)
    const ull Qp0 = ff_pack2(Qg[e * 8 + j0],     Qg[e * 8 + j0 + 1]);
    const ull Qp1 = ff_pack2(Qg[e * 8 + j0 + 2], Qg[e * 8 + j0 + 3]);

    const float r00 = Rg[0], r01 = Rg[1], r11 = Rg[3];

    // ---- per-chain state: half cov row, replicated mean/hm ----
    float cov[4];
    {
        float4 c = *(const float4*)(cov0 + b * 64 + e * 8 + j0);
        cov[0]=c.x; cov[1]=c.y; cov[2]=c.z; cov[3]=c.w;
    }
    float mean_e = mean0[b * 8 + e];
    float hm0, hm1;
    {
        float4 a = *(const float4*)(mean0 + b * 8);
        float4 c = *(const float4*)(mean0 + b * 8 + 4);
        float m[8] = {a.x,a.y,a.z,a.w,c.x,c.y,c.z,c.w};
        float s0 = 0.f, s1 = 0.f;
#pragma unroll
        for (int j = 0; j < 8; ++j) {
            s0 = fmaf(Hg[j],     m[j], s0);
            s1 = fmaf(Hg[8 + j], m[j], s1);
        }
        hm0 = s0; hm1 = s1;
    }

    float* outM = out + OFF_MEANS + (size_t)b * (KF_T * KF_D);
    float* outC = out + OFF_COVS  + (size_t)b * (KF_T * KF_D * KF_D);
    const float* xrow = xin_g + (size_t)b * (KF_T * KF_M);

    // SMEM exchange buffers (bank-conflict-free, verified per access pattern)
    __shared__ __align__(16) float sHP[2 * 16];   // [g]: hp0[0..7]@0, hp1[0..7]@8
    __shared__ __align__(16) float sMu[2 * 8];
    __shared__ __align__(16) float sT1[2 * 72];   // chain stride 72 floats

    float2 x = *(const float2*)xrow;   // prefetch t=0

#pragma unroll 1
    for (int t = 0; t < KF_T; ++t) {
        // emit state BEFORE consuming x_t (1-step-ahead semantics)
        if (h0) outM[t * 8 + e] = mean_e;
        *(float4*)(outC + t * 64 + e * 8 + j0) = make_float4(cov[0], cov[1], cov[2], cov[3]);

        const int tn = (t + 1 < KF_T) ? t + 1 : t;
        const float2 xn = *(const float2*)(xrow + tn * 2);

        // HP[m][e] partial over this half of row e, then combine across h
        float hp0 = 0.f, hp1 = 0.f;
#pragma unroll
        for (int i = 0; i < 4; ++i) {
            hp0 = fmaf(H0h[i], cov[i], hp0);
            hp1 = fmaf(H1h[i], cov[i], hp1);
        }
        hp0 += __shfl_xor_sync(0xffffffffu, hp0, 8);
        hp1 += __shfl_xor_sync(0xffffffffu, hp1, 8);

        if (h0) { sHP[g * 16 + e] = hp0; sHP[g * 16 + 8 + e] = hp1; }
        __syncwarp();

        const float4 Ah = *(const float4*)&sHP[g * 16 + j0];       // hp0[j], j in half
        const float4 Bh = *(const float4*)&sHP[g * 16 + 8 + j0];   // hp1[j]
        const float Aa[4] = {Ah.x, Ah.y, Ah.z, Ah.w};
        const float Bb[4] = {Bh.x, Bh.y, Bh.z, Bh.w};

        // S partials over this half, combine across h
        float S00 = 0.f, S01 = 0.f, S11 = 0.f;
#pragma unroll
        for (int i = 0; i < 4; ++i) {
            S00 = fmaf(H0h[i], Aa[i], S00);
            S01 = fmaf(H1h[i], Aa[i], S01);
            S11 = fmaf(H1h[i], Bb[i], S11);
        }
        S00 = r00 + S00 + __shfl_xor_sync(0xffffffffu, S00, 8);
        S01 = r01 + S01 + __shfl_xor_sync(0xffffffffu, S01, 8);
        S11 = r11 + S11 + __shfl_xor_sync(0xffffffffu, S11, 8);

        const float idet = __fdividef(1.0f, fmaf(S00, S11, -S01 * S01));
        const float Kt0 = (S11 * hp0 - S01 * hp1) * idet;   // Kt[0][e]
        const float Kt1 = (S00 * hp1 - S01 * hp0) * idet;   // Kt[1][e]
        const float rs0 = x.x - hm0;
        const float rs1 = x.y - hm1;
        const float mu  = fmaf(Kt0, rs0, fmaf(Kt1, rs1, mean_e));   // mean_u[e]
        if (h0) sMu[g * 8 + e] = mu;

        // cov_u half-row
        float cu[4];
#pragma unroll
        for (int i = 0; i < 4; ++i)
            cu[i] = cov[i] - Kt0 * Aa[i] - Kt1 * Bb[i];

        // T1[e][:] partial over this lane's k-half (pair-packed), combine across h
        ull tp0 = 0ull, tp1 = 0ull, tp2 = 0ull, tp3 = 0ull;
#pragma unroll
        for (int kk = 0; kk < 4; ++kk) {
            const ull ck = ff_dup(cu[kk]);
            tp0 = ff_fma2(ck, Fpk[kk][0], tp0);
            tp1 = ff_fma2(ck, Fpk[kk][1], tp1);
            tp2 = ff_fma2(ck, Fpk[kk][2], tp2);
            tp3 = ff_fma2(ck, Fpk[kk][3], tp3);
        }
        tp0 = ff_add2(tp0, shflx8_64(tp0));
        tp1 = ff_add2(tp1, shflx8_64(tp1));
        tp2 = ff_add2(tp2, shflx8_64(tp2));
        tp3 = ff_add2(tp3, shflx8_64(tp3));
        // store this lane's j-half of T1 row e (packs 2h, 2h+1)
        {
            const ull sa = h ? tp2 : tp0;
            const ull sb = h ? tp3 : tp1;
            ulonglong2 st; st.x = sa; st.y = sb;
            *(ulonglong2*)&sT1[g * 72 + e * 8 + j0] = st;
        }
        __syncwarp();

        // mean_p / hm partials from mean_u, combine across h
        const float4 Mh = *(const float4*)&sMu[g * 8 + j0];
        const float Mu[4] = {Mh.x, Mh.y, Mh.z, Mh.w};
        float mp = 0.f, nh0 = 0.f, nh1 = 0.f;
#pragma unroll
        for (int i = 0; i < 4; ++i) {
            mp  = fmaf(Frh[i],  Mu[i], mp);
            nh0 = fmaf(HF0h[i], Mu[i], nh0);
            nh1 = fmaf(HF1h[i], Mu[i], nh1);
        }
        mp  += __shfl_xor_sync(0xffffffffu, mp, 8);
        nh0 += __shfl_xor_sync(0xffffffffu, nh0, 8);
        nh1 += __shfl_xor_sync(0xffffffffu, nh1, 8);

        // cov_p[e][half] = sum_k F[e][k] * T1[k][half] + Q[e][half]
        ull cp0 = Qp0, cp1 = Qp1;
#pragma unroll
        for (int k = 0; k < 8; ++k) {
            const ulonglong2 tv = *(const ulonglong2*)&sT1[g * 72 + k * 8 + j0];
            const ull fk = ff_dup(Frow[k]);
            cp0 = ff_fma2(fk, tv.x, cp0);
            cp1 = ff_fma2(fk, tv.y, cp1);
        }
        {
            const float2 c0 = ff_unpack(cp0), c1 = ff_unpack(cp1);
            cov[0] = c0.x; cov[1] = c0.y; cov[2] = c1.x; cov[3] = c1.y;
        }
        mean_e = mp;
        hm0 = nh0; hm1 = nh1;
        x = xn;
        // Race-freedom: sHP/sMu writes sit before syncwarp#1, reads between the
        // two barriers; sT1 writes sit before syncwarp#2, reads after it and
        // before the NEXT iteration's syncwarp#1 (which orders them against the
        // next writes).
    }
}

extern "C" void kernel_launch(void* const* d_in, const int* in_sizes, int n_in,
                              void* d_out, int out_size)
{
    (void)in_sizes; (void)n_in; (void)out_size;
    const float* xin   = (const float*)d_in[0];
    const float* mean0 = (const float*)d_in[1];
    const float* cov0  = (const float*)d_in[2];
    const float* F     = (const float*)d_in[3];
    const float* H     = (const float*)d_in[4];
    const float* Q     = (const float*)d_in[5];
    const float* R     = (const float*)d_in[6];
    float* out = (float*)d_out;

    kf_kernel<<<SCAN_BLOCKS + FILL_BLOCKS, 32>>>(xin, mean0, cov0, F, H, Q, R, out);
}